// round 6
// baseline (speedup 1.0000x reference)
#include <cuda_runtime.h>
#include <cuda_fp16.h>
#include <stdint.h>

#define N_NODES 1000000
#define F 16
#define MAX_E 4000000
#define SCAN_B 1024

// Scratch (allocation-free rule: __device__ globals)
__device__ __half g_h[(size_t)N_NODES * F];   // h = x @ W (fp16, 32MB)
__device__ float  g_dinv[N_NODES];            // rsqrt(deg + 1)
__device__ int    g_cnt[N_NODES];             // histogram, then scatter cursors
__device__ int    g_off[N_NODES + 1];         // CSR offsets (exclusive scan)
__device__ int    g_bsum[(N_NODES + SCAN_B - 1) / SCAN_B];
__device__ int    g_src[MAX_E];               // src ids grouped by dst

// ---------------------------------------------------------------------------
// K0: zero histogram
// ---------------------------------------------------------------------------
__global__ void k_zero(int n) {
    int i = blockIdx.x * blockDim.x + threadIdx.x;
    if (i < n) g_cnt[i] = 0;
}

// ---------------------------------------------------------------------------
// K1: histogram of dst (= degree without self loop)
// ---------------------------------------------------------------------------
__global__ void k_hist(const int* __restrict__ col, int E, int n) {
    int e = blockIdx.x * blockDim.x + threadIdx.x;
    if (e < E) {
        int c = col[e];
        if ((unsigned)c < (unsigned)n) atomicAdd(&g_cnt[c], 1);
    }
}

// ---------------------------------------------------------------------------
// K2a: per-block exclusive scan of g_cnt -> g_off, block totals -> g_bsum
// ---------------------------------------------------------------------------
__global__ void __launch_bounds__(SCAN_B)
k_scan_block(int n) {
    __shared__ int s[SCAN_B];
    int i = blockIdx.x * SCAN_B + threadIdx.x;
    int v = (i < n) ? g_cnt[i] : 0;
    s[threadIdx.x] = v;
    __syncthreads();
#pragma unroll
    for (int d = 1; d < SCAN_B; d <<= 1) {
        int t = (threadIdx.x >= d) ? s[threadIdx.x - d] : 0;
        __syncthreads();
        s[threadIdx.x] += t;
        __syncthreads();
    }
    if (i < n) g_off[i] = s[threadIdx.x] - v;   // exclusive
    if (threadIdx.x == SCAN_B - 1) g_bsum[blockIdx.x] = s[SCAN_B - 1];
}

// ---------------------------------------------------------------------------
// K2b: exclusive scan of block sums (single block; nb <= 1024)
// ---------------------------------------------------------------------------
__global__ void __launch_bounds__(SCAN_B)
k_scan_top(int nb) {
    __shared__ int s[SCAN_B];
    int v = (threadIdx.x < nb) ? g_bsum[threadIdx.x] : 0;
    s[threadIdx.x] = v;
    __syncthreads();
#pragma unroll
    for (int d = 1; d < SCAN_B; d <<= 1) {
        int t = (threadIdx.x >= d) ? s[threadIdx.x - d] : 0;
        __syncthreads();
        s[threadIdx.x] += t;
        __syncthreads();
    }
    if (threadIdx.x < nb) g_bsum[threadIdx.x] = s[threadIdx.x] - v;  // exclusive
}

// ---------------------------------------------------------------------------
// K2c: add block prefixes; compute dinv; write sentinel off[n]=E
// ---------------------------------------------------------------------------
__global__ void k_finish(int n, int E) {
    int i = blockIdx.x * blockDim.x + threadIdx.x;
    if (i < n) {
        g_off[i] += g_bsum[i / SCAN_B];
        g_dinv[i] = rsqrtf((float)g_cnt[i] + 1.0f);
    }
    if (i == 0) g_off[n] = E;
}

// ---------------------------------------------------------------------------
// K3: h = x @ W -> g_h (fp16). Pure streaming.
// ---------------------------------------------------------------------------
__global__ void __launch_bounds__(256)
k_h(const float4* __restrict__ x4, const float* __restrict__ W, int n) {
    __shared__ float sW[F * F];
    if (threadIdx.x < F * F) sW[threadIdx.x] = W[threadIdx.x];
    __syncthreads();

    int i = blockIdx.x * blockDim.x + threadIdx.x;
    if (i >= n) return;

    float4 xv0 = x4[(size_t)i * 4 + 0];
    float4 xv1 = x4[(size_t)i * 4 + 1];
    float4 xv2 = x4[(size_t)i * 4 + 2];
    float4 xv3 = x4[(size_t)i * 4 + 3];
    float xr[F] = {xv0.x, xv0.y, xv0.z, xv0.w,
                   xv1.x, xv1.y, xv1.z, xv1.w,
                   xv2.x, xv2.y, xv2.z, xv2.w,
                   xv3.x, xv3.y, xv3.z, xv3.w};

    float acc[F];
#pragma unroll
    for (int j = 0; j < F; j++) acc[j] = 0.0f;
#pragma unroll
    for (int k = 0; k < F; k++) {
        float xk = xr[k];
#pragma unroll
        for (int j = 0; j < F; j++) acc[j] = fmaf(xk, sW[k * F + j], acc[j]);
    }

    uint4 hpk[2];
    __half2* hh = reinterpret_cast<__half2*>(&hpk[0]);
#pragma unroll
    for (int q = 0; q < 8; q++)
        hh[q] = __floats2half2_rn(acc[2 * q], acc[2 * q + 1]);
    uint4* hp = reinterpret_cast<uint4*>(g_h + (size_t)i * F);
    hp[0] = hpk[0];
    hp[1] = hpk[1];
}

// ---------------------------------------------------------------------------
// K4: scatter src ids into dst-grouped buffer (slot via histogram decrement)
// ---------------------------------------------------------------------------
__global__ void k_scatter(const int* __restrict__ ei, int E, int n) {
    int e = blockIdx.x * blockDim.x + threadIdx.x;
    if (e >= E) return;
    int r = ei[e];
    int c = ei[(size_t)E + e];
    if ((unsigned)r >= (unsigned)n || (unsigned)c >= (unsigned)n) return;
    int k = atomicSub(&g_cnt[c], 1) - 1;   // unique slot 0..deg-1
    g_src[g_off[c] + k] = r;
}

// ---------------------------------------------------------------------------
// K5: per-dst gather, 4 THREADS PER NODE (feature split).
// Group lane q owns features [4q, 4q+4) = 4 halves = 8 BYTES (uint2).
// Per edge all 4 lanes load the same src idx/dinv (L1 broadcast) and one 8B
// quarter of the 32B fp16 h-row: together one contiguous 32B access.
// No cross-thread reduction; each lane writes its float4 of out.
// ---------------------------------------------------------------------------
__global__ void __launch_bounds__(256)
k_out(const float* __restrict__ b, float4* __restrict__ out4, int n) {
    int tid  = threadIdx.x;
    int lane = tid & 3;                       // quarter index
    int i    = blockIdx.x * 64 + (tid >> 2);  // node
    if (i >= n) return;

    float4 bq = reinterpret_cast<const float4*>(b)[lane];

    int s0 = __ldg(&g_off[i]);
    int s1 = __ldg(&g_off[i + 1]);
    float di = g_dinv[i];

    float4 acc = make_float4(0.f, 0.f, 0.f, 0.f);

    int j = s0;
    // unroll-2 main loop
    for (; j + 2 <= s1; j += 2) {
        int sA = __ldg(&g_src[j]);
        int sB = __ldg(&g_src[j + 1]);
        float dA = __ldg(&g_dinv[sA]);
        float dB = __ldg(&g_dinv[sB]);
        uint2 pA = __ldg(&reinterpret_cast<const uint2*>(g_h + (size_t)sA * F)[lane]);
        uint2 pB = __ldg(&reinterpret_cast<const uint2*>(g_h + (size_t)sB * F)[lane]);
        float2 a0 = __half22float2(*reinterpret_cast<const __half2*>(&pA.x));
        float2 a1 = __half22float2(*reinterpret_cast<const __half2*>(&pA.y));
        float2 b0 = __half22float2(*reinterpret_cast<const __half2*>(&pB.x));
        float2 b1 = __half22float2(*reinterpret_cast<const __half2*>(&pB.y));
        acc.x = fmaf(a0.x, dA, fmaf(b0.x, dB, acc.x));
        acc.y = fmaf(a0.y, dA, fmaf(b0.y, dB, acc.y));
        acc.z = fmaf(a1.x, dA, fmaf(b1.x, dB, acc.z));
        acc.w = fmaf(a1.y, dA, fmaf(b1.y, dB, acc.w));
    }
    if (j < s1) {
        int s = __ldg(&g_src[j]);
        float ds = __ldg(&g_dinv[s]);
        uint2 p = __ldg(&reinterpret_cast<const uint2*>(g_h + (size_t)s * F)[lane]);
        float2 f0 = __half22float2(*reinterpret_cast<const __half2*>(&p.x));
        float2 f1 = __half22float2(*reinterpret_cast<const __half2*>(&p.y));
        acc.x = fmaf(f0.x, ds, acc.x);
        acc.y = fmaf(f0.y, ds, acc.y);
        acc.z = fmaf(f1.x, ds, acc.z);
        acc.w = fmaf(f1.y, ds, acc.w);
    }

    // self-loop quarter from fp16 h[i]
    uint2 pi = reinterpret_cast<const uint2*>(g_h + (size_t)i * F)[lane];
    float2 v0 = __half22float2(*reinterpret_cast<const __half2*>(&pi.x));
    float2 v1 = __half22float2(*reinterpret_cast<const __half2*>(&pi.y));

    float dii = di * di;
    out4[(size_t)i * 4 + lane] = make_float4(
        fmaf(acc.x, di, fmaf(v0.x, dii, bq.x)),
        fmaf(acc.y, di, fmaf(v0.y, dii, bq.y)),
        fmaf(acc.z, di, fmaf(v1.x, dii, bq.z)),
        fmaf(acc.w, di, fmaf(v1.y, dii, bq.w)));
}

// ---------------------------------------------------------------------------
// launch
// ---------------------------------------------------------------------------
extern "C" void kernel_launch(void* const* d_in, const int* in_sizes, int n_in,
                              void* d_out, int out_size) {
    const float* x   = (const float*)d_in[0];
    const int*   ei  = (const int*)d_in[1];  // int32 (JAX x64 disabled)
    const float* W   = (const float*)d_in[2];
    const float* b   = (const float*)d_in[3];
    float*       out = (float*)d_out;

    int n = in_sizes[0] / F;   // 1,000,000
    int E = in_sizes[1] / 2;   // 4,000,000
    if (E > MAX_E) E = MAX_E;

    const int T = 256;
    int nb = (n + SCAN_B - 1) / SCAN_B;

    k_zero<<<(n + T - 1) / T, T>>>(n);
    k_hist<<<(E + T - 1) / T, T>>>(ei + (size_t)E, E, n);
    k_scan_block<<<nb, SCAN_B>>>(n);
    k_scan_top<<<1, SCAN_B>>>(nb);
    k_finish<<<(n + T - 1) / T, T>>>(n, E);
    k_h<<<(n + T - 1) / T, T>>>((const float4*)x, W, n);
    k_scatter<<<(E + T - 1) / T, T>>>(ei, E, n);
    k_out<<<(n * 4 + T - 1) / T, T>>>(b, (float4*)out, n);
}